// round 13
// baseline (speedup 1.0000x reference)
#include <cuda_runtime.h>
#include <cuda_bf16.h>
#include <cuda_fp16.h>
#include <cstdint>
#include <cstddef>

// ---------------------------------------------------------------------------
// CrossLayerLateral: out = x_current + alpha * (x_prev @ W^T), W from COO.
// compute_100 (no tcgen05/TMA): cp.async + ldmatrix + FP8 e4m3 mma.sync
// m16n8k32, f16 acc, 64x64 warp tiles. R12 analysis: barrier-forced ldsm
// phase alignment costs ~26% tensor idle. This round: warp-private smem
// stages + per-warp cp.async pacing -> ZERO barriers in the mainloop.
// Preprocessing reverted to proven R10 path (fp32 scatter).
// ---------------------------------------------------------------------------

#define HID 2048
#define MROWS_MAX 8192
#define BM 128
#define BN 128
#define BK 64                   // fp8 bytes per K-chunk (64B rows in smem)
#define WSTAGES 3               // per-warp stages
#define NKT (HID / BK)          // 32
#define WSCALE 512.0f
#define NTHREADS 128

#define WARP_STAGE_BYTES 8192   // A 64x64B (4KB) + B 64x64B (4KB)
#define WARP_SMEM (WSTAGES * WARP_STAGE_BYTES)      // 24576
#define SMEM_BYTES (4 * WARP_SMEM)                  // 98304

// -------------------- device scratch (static: no allocs) -------------------
__device__ float   g_Wf[HID * HID];            // 16 MB fp32 dense W
__device__ uint8_t g_Wq[HID * HID];            // 4 MB e4m3 W*512, [i][j] j contig
__device__ uint8_t g_Xq[MROWS_MAX * HID];      // 16 MB e4m3 x_prev

// -------------------- preprocessing (R10 proven path) -----------------------
__device__ __forceinline__ uint16_t f2_to_e4m3x2(float lo, float hi) {
    uint16_t p;
    asm("cvt.rn.satfinite.e4m3x2.f32 %0, %1, %2;" : "=h"(p) : "f"(hi), "f"(lo));
    return p;
}

__global__ void zero_and_convx_kernel(const float* __restrict__ src, int n16) {
    const int gsz = gridDim.x * blockDim.x;
    for (int i = blockIdx.x * blockDim.x + threadIdx.x; i < HID * HID / 4; i += gsz)
        reinterpret_cast<float4*>(g_Wf)[i] = make_float4(0.f, 0.f, 0.f, 0.f);
    for (int i = blockIdx.x * blockDim.x + threadIdx.x; i < n16; i += gsz) {
        uint32_t o[4];
#pragma unroll
        for (int q = 0; q < 4; q++) {
            float4 v = reinterpret_cast<const float4*>(src)[4 * i + q];
            o[q] = (uint32_t)f2_to_e4m3x2(v.x, v.y) |
                   ((uint32_t)f2_to_e4m3x2(v.z, v.w) << 16);
        }
        reinterpret_cast<uint4*>(g_Xq)[i] = make_uint4(o[0], o[1], o[2], o[3]);
    }
}

__global__ void scatter_kernel(const int* __restrict__ idx,
                               const float* __restrict__ val, int nnz) {
    int k = blockIdx.x * blockDim.x + threadIdx.x;
    if (k < nnz) {
        int i = idx[k];
        int j = idx[nnz + k];
        atomicAdd(&g_Wf[(size_t)i * HID + j], val[k]);
    }
}

__global__ void conv_w_kernel() {
    int i = blockIdx.x * blockDim.x + threadIdx.x;
    if (i < HID * HID / 16) {
        uint32_t o[4];
#pragma unroll
        for (int q = 0; q < 4; q++) {
            float4 v = reinterpret_cast<const float4*>(g_Wf)[4 * i + q];
            o[q] = (uint32_t)f2_to_e4m3x2(v.x * WSCALE, v.y * WSCALE) |
                   ((uint32_t)f2_to_e4m3x2(v.z * WSCALE, v.w * WSCALE) << 16);
        }
        reinterpret_cast<uint4*>(g_Wq)[i] = make_uint4(o[0], o[1], o[2], o[3]);
    }
}

// -------------------- GEMM helpers ------------------------------------------
__device__ __forceinline__ void cp_async16(uint32_t dst, const void* src) {
    asm volatile("cp.async.cg.shared.global [%0], [%1], 16;" :: "r"(dst), "l"(src));
}
__device__ __forceinline__ void cp_commit() {
    asm volatile("cp.async.commit_group;" ::: "memory");
}
template <int N>
__device__ __forceinline__ void cp_wait() {
    asm volatile("cp.async.wait_group %0;" :: "n"(N) : "memory");
}

__device__ __forceinline__ void ldsm_x4(uint32_t& r0, uint32_t& r1, uint32_t& r2,
                                        uint32_t& r3, uint32_t addr) {
    asm volatile("ldmatrix.sync.aligned.m8n8.x4.shared.b16 {%0,%1,%2,%3}, [%4];"
                 : "=r"(r0), "=r"(r1), "=r"(r2), "=r"(r3) : "r"(addr));
}

__device__ __forceinline__ void mma_fp8_f16(uint32_t& c0, uint32_t& c1,
                                            uint32_t a0, uint32_t a1, uint32_t a2, uint32_t a3,
                                            uint32_t b0, uint32_t b1) {
    asm volatile(
        "mma.sync.aligned.m16n8k32.row.col.f16.e4m3.e4m3.f16 "
        "{%0,%1}, {%2,%3,%4,%5}, {%6,%7}, {%0,%1};"
        : "+r"(c0), "+r"(c1)
        : "r"(a0), "r"(a1), "r"(a2), "r"(a3), "r"(b0), "r"(b1));
}

// SW64 swizzle: chunk c (16B) of 64B row r -> r*64 + ((c ^ ((r>>1)&3))*16)
__device__ __forceinline__ uint32_t sw64(uint32_t row, uint32_t c) {
    return row * 64u + (((c ^ (row >> 1)) & 3u) * 16u);
}

// -------------------- GEMM kernel (barrier-free mainloop) -------------------
__global__ __launch_bounds__(NTHREADS, 2)
void gemm_kernel(const float* __restrict__ x_cur,
                 const float* __restrict__ alpha_p,
                 float* __restrict__ out) {
    extern __shared__ char smraw[];
    const int tid  = threadIdx.x;
    const int wid  = tid >> 5;
    const int lane = tid & 31;
    const int n0 = blockIdx.x * BN;
    const int m0 = blockIdx.y * BM;
    const int rm = (wid & 1) * 64;          // this warp's 64x64 output tile
    const int rn = ((wid >> 1) & 1) * 64;

    uint32_t smem;
    asm("{ .reg .u64 t; cvta.to.shared.u64 t, %1; cvt.u32.u64 %0, t; }"
        : "=r"(smem) : "l"(smraw));
    const uint32_t wbase = smem + (uint32_t)wid * WARP_SMEM;

    // ---- per-lane cp.async addressing: 8 A-chunks + 8 B-chunks per stage ----
    // lane -> base row lr = lane>>2 (rows lr, lr+8, ..., lr+56), fixed 16B
    // chunk c = lane&3. Each warp loads its OWN A rows [rm,rm+64) and B rows
    // [rn,rn+64).
    const uint32_t lr = (uint32_t)(lane >> 2);
    const uint32_t cc = (uint32_t)(lane & 3);
    const uint8_t* gA = g_Xq + (size_t)(m0 + rm + lr) * HID + cc * 16;
    const uint8_t* gB = g_Wq + (size_t)(n0 + rn + lr) * HID + cc * 16;
    uint32_t sA[8], sB[8];
#pragma unroll
    for (int i = 0; i < 8; i++) {
        uint32_t row = lr + (uint32_t)i * 8u;
        sA[i] = wbase + sw64(row, cc);
        sB[i] = wbase + 4096u + sw64(row, cc);
    }

    // ---- per-lane ldsm addressing (local rows 0..63 in warp buffer) ----
    const uint32_t lc = (uint32_t)(lane >> 4);
    uint32_t aAddr[4], aSw[4], bAddr[4], bSw[4];
#pragma unroll
    for (int f = 0; f < 4; f++) {
        uint32_t r = (uint32_t)((lane & 15) + f * 16);
        aAddr[f] = wbase + r * 64u;
        bAddr[f] = wbase + 4096u + r * 64u;
        aSw[f] = (r >> 1) & 3u;
        bSw[f] = aSw[f];
    }

    uint32_t acc[4][8][2];
#pragma unroll
    for (int mf = 0; mf < 4; mf++)
#pragma unroll
        for (int nf = 0; nf < 8; nf++) {
            acc[mf][nf][0] = 0u; acc[mf][nf][1] = 0u;
        }

    // ---- prologue: issue stages for kt=0,1 (per-warp) ----
#pragma unroll
    for (int st = 0; st < 2; st++) {
        const uint32_t so = (uint32_t)st * WARP_STAGE_BYTES;
#pragma unroll
        for (int i = 0; i < 8; i++) {
            cp_async16(sA[i] + so, gA + st * BK + i * 8 * HID);
            cp_async16(sB[i] + so, gB + st * BK + i * 8 * HID);
        }
        cp_commit();
    }

    uint32_t slot = 0;  // kt % 3 tracked incrementally
    for (int kt = 0; kt < NKT; kt++) {
        const uint32_t sOff = slot * WARP_STAGE_BYTES;

        // ---- wait for stage kt (leave 1 group in flight) ----
        if (kt + 2 < NKT) cp_wait<1>(); else cp_wait<0>();

        // ---- ldsm all fragments for this stage ----
        uint32_t a0[4][4], b0[4][4], a1[4][4], b1[4][4];
#pragma unroll
        for (int mf = 0; mf < 4; mf++)
            ldsm_x4(a0[mf][0], a0[mf][1], a0[mf][2], a0[mf][3],
                    aAddr[mf] + sOff + (((lc ^ aSw[mf]) & 3u) << 4));
#pragma unroll
        for (int bf = 0; bf < 4; bf++)
            ldsm_x4(b0[bf][0], b0[bf][1], b0[bf][2], b0[bf][3],
                    bAddr[bf] + sOff + (((lc ^ bSw[bf]) & 3u) << 4));
#pragma unroll
        for (int mf = 0; mf < 4; mf++)
            ldsm_x4(a1[mf][0], a1[mf][1], a1[mf][2], a1[mf][3],
                    aAddr[mf] + sOff + ((((2 + lc) ^ aSw[mf]) & 3u) << 4));
#pragma unroll
        for (int bf = 0; bf < 4; bf++)
            ldsm_x4(b1[bf][0], b1[bf][1], b1[bf][2], b1[bf][3],
                    bAddr[bf] + sOff + ((((2 + lc) ^ bSw[bf]) & 3u) << 4));

        // ---- issue stage kt+2 into slot (kt+2)%3 (its readers: iter kt-1) ----
        if (kt + 2 < NKT) {
            uint32_t ps = slot + 2u; if (ps >= 3u) ps -= 3u;
            const uint32_t pOff = ps * WARP_STAGE_BYTES;
            const uint8_t* pa = gA + (kt + 2) * BK;
            const uint8_t* pb = gB + (kt + 2) * BK;
#pragma unroll
            for (int i = 0; i < 8; i++) {
                cp_async16(sA[i] + pOff, pa + i * 8 * HID);
                cp_async16(sB[i] + pOff, pb + i * 8 * HID);
            }
            cp_commit();
        }

        // ---- 64 mmas ----
#pragma unroll
        for (int mf = 0; mf < 4; mf++)
#pragma unroll
            for (int bf = 0; bf < 4; bf++) {
                mma_fp8_f16(acc[mf][2 * bf][0], acc[mf][2 * bf][1],
                            a0[mf][0], a0[mf][1], a0[mf][2], a0[mf][3],
                            b0[bf][0], b0[bf][2]);
                mma_fp8_f16(acc[mf][2 * bf + 1][0], acc[mf][2 * bf + 1][1],
                            a0[mf][0], a0[mf][1], a0[mf][2], a0[mf][3],
                            b0[bf][1], b0[bf][3]);
            }
#pragma unroll
        for (int mf = 0; mf < 4; mf++)
#pragma unroll
            for (int bf = 0; bf < 4; bf++) {
                mma_fp8_f16(acc[mf][2 * bf][0], acc[mf][2 * bf][1],
                            a1[mf][0], a1[mf][1], a1[mf][2], a1[mf][3],
                            b1[bf][0], b1[bf][2]);
                mma_fp8_f16(acc[mf][2 * bf + 1][0], acc[mf][2 * bf + 1][1],
                            a1[mf][0], a1[mf][1], a1[mf][2], a1[mf][3],
                            b1[bf][1], b1[bf][3]);
            }

        slot = (slot + 1u == 3u) ? 0u : slot + 1u;
    }

    // -------------------- fused epilogue: out = x_cur + (alpha/512)*acc ----
    // acc is warp-private; no synchronization needed.
    const float alpha = __ldg(alpha_p) * (1.0f / WSCALE);
#pragma unroll
    for (int mf = 0; mf < 4; mf++) {
        const int r = m0 + rm + mf * 16 + (lane >> 2);
#pragma unroll
        for (int nf = 0; nf < 8; nf++) {
            const int cidx = n0 + rn + nf * 8 + (lane & 3) * 2;
            size_t g0 = (size_t)r * HID + cidx;
            float2 v0 = __half22float2(*reinterpret_cast<__half2*>(&acc[mf][nf][0]));
            float2 x0 = *reinterpret_cast<const float2*>(x_cur + g0);
            float2 o0;
            o0.x = fmaf(alpha, v0.x, x0.x);
            o0.y = fmaf(alpha, v0.y, x0.y);
            *reinterpret_cast<float2*>(out + g0) = o0;
            size_t g1 = g0 + (size_t)8 * HID;
            float2 v1 = __half22float2(*reinterpret_cast<__half2*>(&acc[mf][nf][1]));
            float2 x1 = *reinterpret_cast<const float2*>(x_cur + g1);
            float2 o1;
            o1.x = fmaf(alpha, v1.x, x1.x);
            o1.y = fmaf(alpha, v1.y, x1.y);
            *reinterpret_cast<float2*>(out + g1) = o1;
        }
    }
}

// -------------------- launcher ---------------------------------------------
extern "C" void kernel_launch(void* const* d_in, const int* in_sizes, int n_in,
                              void* d_out, int out_size) {
    const float* x_cur  = (const float*)d_in[0];
    const float* x_prev = (const float*)d_in[1];
    const float* alpha  = (const float*)d_in[2];
    const float* vals   = (const float*)d_in[3];
    const int*   idx    = (const int*)d_in[4];
    const int nnz   = in_sizes[3];
    const int mrows = in_sizes[0] / HID;     // 8192

    cudaFuncSetAttribute(gemm_kernel,
                         cudaFuncAttributeMaxDynamicSharedMemorySize, SMEM_BYTES);

    const int n16x = mrows * HID / 16;
    zero_and_convx_kernel<<<2048, 256>>>(x_prev, n16x);
    scatter_kernel<<<(nnz + 255) / 256, 256>>>(idx, vals, nnz);
    conv_w_kernel<<<(HID * HID / 16 + 255) / 256, 256>>>();

    dim3 grid(HID / BN, mrows / BM);         // 16 x 64 = 1024 CTAs
    gemm_kernel<<<grid, NTHREADS, SMEM_BYTES>>>(x_cur, alpha, (float*)d_out);
}

// round 14
// speedup vs baseline: 1.0266x; 1.0266x over previous
#include <cuda_runtime.h>
#include <cuda_bf16.h>
#include <cuda_fp16.h>
#include <cstdint>
#include <cstddef>

// ---------------------------------------------------------------------------
// CrossLayerLateral: out = x_current + alpha * (x_prev @ W^T), W from COO.
// compute_100 (no tcgen05/TMA): cp.async + ldmatrix + FP8 e4m3 mma.sync
// m16n8k32, f16 acc, 64x64 warp tiles, 4-stage pipeline (R10 skeleton).
// This round: manual ldsm/mma interleave (asm volatile preserves source
// order, so we schedule explicitly). Loop top has ZERO ldsm: each 8-ldsm
// group is hidden between 16-mma blocks; next-kt fragments load into the
// dead a0/b0 registers during the h1 mma stream.
// ---------------------------------------------------------------------------

#define HID 2048
#define MROWS_MAX 8192
#define BM 128
#define BN 128
#define BK 64                   // fp8 bytes per K-chunk (64B rows in smem)
#define STAGES 4
#define NKT (HID / BK)          // 32
#define WSCALE 512.0f
#define NTHREADS 128

#define A_STAGE_BYTES (BM * BK)         // 8192
#define B_STAGE_BYTES (BN * BK)         // 8192
#define B_REGION_OFF  (STAGES * A_STAGE_BYTES)
#define SMEM_BYTES    (STAGES * (A_STAGE_BYTES + B_STAGE_BYTES))   // 65536

// -------------------- device scratch (static: no allocs) -------------------
__device__ float   g_Wf[HID * HID];            // 16 MB fp32 dense W
__device__ uint8_t g_Wq[HID * HID];            // 4 MB e4m3 W*512, [i][j] j contig
__device__ uint8_t g_Xq[MROWS_MAX * HID];      // 16 MB e4m3 x_prev

// -------------------- preprocessing (R10 proven path) -----------------------
__device__ __forceinline__ uint16_t f2_to_e4m3x2(float lo, float hi) {
    uint16_t p;
    asm("cvt.rn.satfinite.e4m3x2.f32 %0, %1, %2;" : "=h"(p) : "f"(hi), "f"(lo));
    return p;
}

__global__ void zero_and_convx_kernel(const float* __restrict__ src, int n16) {
    const int gsz = gridDim.x * blockDim.x;
    for (int i = blockIdx.x * blockDim.x + threadIdx.x; i < HID * HID / 4; i += gsz)
        reinterpret_cast<float4*>(g_Wf)[i] = make_float4(0.f, 0.f, 0.f, 0.f);
    for (int i = blockIdx.x * blockDim.x + threadIdx.x; i < n16; i += gsz) {
        uint32_t o[4];
#pragma unroll
        for (int q = 0; q < 4; q++) {
            float4 v = reinterpret_cast<const float4*>(src)[4 * i + q];
            o[q] = (uint32_t)f2_to_e4m3x2(v.x, v.y) |
                   ((uint32_t)f2_to_e4m3x2(v.z, v.w) << 16);
        }
        reinterpret_cast<uint4*>(g_Xq)[i] = make_uint4(o[0], o[1], o[2], o[3]);
    }
}

__global__ void scatter_kernel(const int* __restrict__ idx,
                               const float* __restrict__ val, int nnz) {
    int k = blockIdx.x * blockDim.x + threadIdx.x;
    if (k < nnz) {
        int i = idx[k];
        int j = idx[nnz + k];
        atomicAdd(&g_Wf[(size_t)i * HID + j], val[k]);
    }
}

__global__ void conv_w_kernel() {
    int i = blockIdx.x * blockDim.x + threadIdx.x;
    if (i < HID * HID / 16) {
        uint32_t o[4];
#pragma unroll
        for (int q = 0; q < 4; q++) {
            float4 v = reinterpret_cast<const float4*>(g_Wf)[4 * i + q];
            o[q] = (uint32_t)f2_to_e4m3x2(v.x * WSCALE, v.y * WSCALE) |
                   ((uint32_t)f2_to_e4m3x2(v.z * WSCALE, v.w * WSCALE) << 16);
        }
        reinterpret_cast<uint4*>(g_Wq)[i] = make_uint4(o[0], o[1], o[2], o[3]);
    }
}

// -------------------- GEMM helpers ------------------------------------------
__device__ __forceinline__ void cp_async16(uint32_t dst, const void* src) {
    asm volatile("cp.async.cg.shared.global [%0], [%1], 16;" :: "r"(dst), "l"(src));
}
__device__ __forceinline__ void cp_commit() {
    asm volatile("cp.async.commit_group;" ::: "memory");
}
template <int N>
__device__ __forceinline__ void cp_wait() {
    asm volatile("cp.async.wait_group %0;" :: "n"(N) : "memory");
}

__device__ __forceinline__ void ldsm_x4(uint32_t& r0, uint32_t& r1, uint32_t& r2,
                                        uint32_t& r3, uint32_t addr) {
    asm volatile("ldmatrix.sync.aligned.m8n8.x4.shared.b16 {%0,%1,%2,%3}, [%4];"
                 : "=r"(r0), "=r"(r1), "=r"(r2), "=r"(r3) : "r"(addr));
}

__device__ __forceinline__ void mma_fp8_f16(uint32_t& c0, uint32_t& c1,
                                            uint32_t a0, uint32_t a1, uint32_t a2, uint32_t a3,
                                            uint32_t b0, uint32_t b1) {
    asm volatile(
        "mma.sync.aligned.m16n8k32.row.col.f16.e4m3.e4m3.f16 "
        "{%0,%1}, {%2,%3,%4,%5}, {%6,%7}, {%0,%1};"
        : "+r"(c0), "+r"(c1)
        : "r"(a0), "r"(a1), "r"(a2), "r"(a3), "r"(b0), "r"(b1));
}

// SW64 swizzle: chunk c (16B) of 64B row r -> r*64 + ((c ^ ((r>>1)&3))*16)
__device__ __forceinline__ uint32_t sw64(uint32_t row, uint32_t c) {
    return row * 64u + (((c ^ (row >> 1)) & 3u) * 16u);
}

// -------------------- GEMM kernel -------------------------------------------
__global__ __launch_bounds__(NTHREADS, 2)
void gemm_kernel(const float* __restrict__ x_cur,
                 const float* __restrict__ alpha_p,
                 float* __restrict__ out) {
    extern __shared__ char smraw[];
    const int tid  = threadIdx.x;
    const int wid  = tid >> 5;
    const int lane = tid & 31;
    const int n0 = blockIdx.x * BN;
    const int m0 = blockIdx.y * BM;
    const int rm = (wid & 1) * 64;          // warp tile 64x64
    const int rn = ((wid >> 1) & 1) * 64;

    uint32_t smem;
    asm("{ .reg .u64 t; cvta.to.shared.u64 t, %1; cvt.u32.u64 %0, t; }"
        : "=r"(smem) : "l"(smraw));

    // ---- precomputed cp.async addressing (8 chunks per thread) ----
    const uint8_t* gp[8];
    uint32_t dsto[8];
#pragma unroll
    for (int i = 0; i < 8; i++) {
        int t = tid + i * NTHREADS;    // 0..1023; A: [0,512), B: [512,1024)
        bool isB = t >= 512;
        uint32_t u = (uint32_t)(isB ? t - 512 : t);
        uint32_t row = u >> 2, c = u & 3;
        gp[i] = (isB ? g_Wq + (size_t)(n0 + row) * HID
                     : g_Xq + (size_t)(m0 + row) * HID) + c * 16;
        dsto[i] = smem + (isB ? B_REGION_OFF : 0u) + sw64(row, c);
    }

    // ---- precomputed ldsm addressing ----
    const uint32_t lc = (uint32_t)(lane >> 4);
    uint32_t aRow[4], aSw[4], bRow[4], bSw[4];
#pragma unroll
    for (int mf = 0; mf < 4; mf++) {
        uint32_t r = (uint32_t)(rm + (lane & 15) + mf * 16);
        aRow[mf] = smem + r * 64u;
        aSw[mf]  = (r >> 1) & 3u;
    }
#pragma unroll
    for (int bf = 0; bf < 4; bf++) {
        uint32_t r = (uint32_t)(rn + (lane & 15) + bf * 16);
        bRow[bf] = smem + B_REGION_OFF + r * 64u;
        bSw[bf]  = (r >> 1) & 3u;
    }

    uint32_t acc[4][8][2];
#pragma unroll
    for (int mf = 0; mf < 4; mf++)
#pragma unroll
        for (int nf = 0; nf < 8; nf++) {
            acc[mf][nf][0] = 0u; acc[mf][nf][1] = 0u;
        }

    // ---- prologue: issue stages 0,1,2 ----
#pragma unroll
    for (int st = 0; st < 3; st++) {
#pragma unroll
        for (int i = 0; i < 8; i++)
            cp_async16(dsto[i] + (uint32_t)st * 8192u, gp[i] + st * BK);
        cp_commit();
    }
    cp_wait<2>();
    __syncthreads();

    // Fragment sets (a0/b0 = current-kt half0, a1/b1 = current-kt half1).
    uint32_t a0[4][4], b0[4][4], a1[4][4], b1[4][4];

    // ---- prime: ldsm (kt=0, half0) -- the only exposed ldsm burst ----
#pragma unroll
    for (int mf = 0; mf < 4; mf++)
        ldsm_x4(a0[mf][0], a0[mf][1], a0[mf][2], a0[mf][3],
                aRow[mf] + (((lc ^ aSw[mf]) & 3u) << 4));
#pragma unroll
    for (int bf = 0; bf < 4; bf++)
        ldsm_x4(b0[bf][0], b0[bf][1], b0[bf][2], b0[bf][3],
                bRow[bf] + (((lc ^ bSw[bf]) & 3u) << 4));

    for (int kt = 0; kt < NKT; kt++) {
        const uint32_t sOff = (uint32_t)(kt & (STAGES - 1)) * 8192u;
        const uint32_t nOff = (uint32_t)((kt + 1) & (STAGES - 1)) * 8192u;

        // ---- prefetch stage kt+3 (slot (kt-1)%4; readers done pre-(kt-1)'s sync)
        if (kt + 3 < NKT) {
            const uint32_t pOff = (uint32_t)((kt + 3) & (STAGES - 1)) * 8192u;
#pragma unroll
            for (int i = 0; i < 8; i++)
                cp_async16(dsto[i] + pOff, gp[i] + (kt + 3) * BK);
            cp_commit();
        }

        // ---- mma h0 part 1 (mf 0..1, 16 mmas) ----
#pragma unroll
        for (int mf = 0; mf < 2; mf++)
#pragma unroll
            for (int bf = 0; bf < 4; bf++) {
                mma_fp8_f16(acc[mf][2 * bf][0], acc[mf][2 * bf][1],
                            a0[mf][0], a0[mf][1], a0[mf][2], a0[mf][3],
                            b0[bf][0], b0[bf][2]);
                mma_fp8_f16(acc[mf][2 * bf + 1][0], acc[mf][2 * bf + 1][1],
                            a0[mf][0], a0[mf][1], a0[mf][2], a0[mf][3],
                            b0[bf][1], b0[bf][3]);
            }

        // ---- ldsm (kt, half1) hidden between mma blocks ----
#pragma unroll
        for (int mf = 0; mf < 4; mf++)
            ldsm_x4(a1[mf][0], a1[mf][1], a1[mf][2], a1[mf][3],
                    aRow[mf] + sOff + ((((2 + lc) ^ aSw[mf]) & 3u) << 4));
#pragma unroll
        for (int bf = 0; bf < 4; bf++)
            ldsm_x4(b1[bf][0], b1[bf][1], b1[bf][2], b1[bf][3],
                    bRow[bf] + sOff + ((((2 + lc) ^ bSw[bf]) & 3u) << 4));

        // ---- mma h0 part 2 (mf 2..3, 16 mmas) ----
#pragma unroll
        for (int mf = 2; mf < 4; mf++)
#pragma unroll
            for (int bf = 0; bf < 4; bf++) {
                mma_fp8_f16(acc[mf][2 * bf][0], acc[mf][2 * bf][1],
                            a0[mf][0], a0[mf][1], a0[mf][2], a0[mf][3],
                            b0[bf][0], b0[bf][2]);
                mma_fp8_f16(acc[mf][2 * bf + 1][0], acc[mf][2 * bf + 1][1],
                            a0[mf][0], a0[mf][1], a0[mf][2], a0[mf][3],
                            b0[bf][1], b0[bf][3]);
            }

        // ---- stage kt+1 ready + visible after this; slots safe for kt+1 cp --
        if (kt + 3 < NKT) cp_wait<2>(); else cp_wait<0>();
        __syncthreads();

        // ---- mma h1 part 1 (mf 0..1) ----
#pragma unroll
        for (int mf = 0; mf < 2; mf++)
#pragma unroll
            for (int bf = 0; bf < 4; bf++) {
                mma_fp8_f16(acc[mf][2 * bf][0], acc[mf][2 * bf][1],
                            a1[mf][0], a1[mf][1], a1[mf][2], a1[mf][3],
                            b1[bf][0], b1[bf][2]);
                mma_fp8_f16(acc[mf][2 * bf + 1][0], acc[mf][2 * bf + 1][1],
                            a1[mf][0], a1[mf][1], a1[mf][2], a1[mf][3],
                            b1[bf][1], b1[bf][3]);
            }

        // ---- ldsm (kt+1, half0) into dead a0/b0 regs, hidden in h1 stream --
        if (kt + 1 < NKT) {
#pragma unroll
            for (int mf = 0; mf < 4; mf++)
                ldsm_x4(a0[mf][0], a0[mf][1], a0[mf][2], a0[mf][3],
                        aRow[mf] + nOff + (((lc ^ aSw[mf]) & 3u) << 4));
#pragma unroll
            for (int bf = 0; bf < 4; bf++)
                ldsm_x4(b0[bf][0], b0[bf][1], b0[bf][2], b0[bf][3],
                        bRow[bf] + nOff + (((lc ^ bSw[bf]) & 3u) << 4));
        }

        // ---- mma h1 part 2 (mf 2..3) ----
#pragma unroll
        for (int mf = 2; mf < 4; mf++)
#pragma unroll
            for (int bf = 0; bf < 4; bf++) {
                mma_fp8_f16(acc[mf][2 * bf][0], acc[mf][2 * bf][1],
                            a1[mf][0], a1[mf][1], a1[mf][2], a1[mf][3],
                            b1[bf][0], b1[bf][2]);
                mma_fp8_f16(acc[mf][2 * bf + 1][0], acc[mf][2 * bf + 1][1],
                            a1[mf][0], a1[mf][1], a1[mf][2], a1[mf][3],
                            b1[bf][1], b1[bf][3]);
            }
    }

    // -------------------- fused epilogue: out = x_cur + (alpha/512)*acc ----
    const float alpha = __ldg(alpha_p) * (1.0f / WSCALE);
#pragma unroll
    for (int mf = 0; mf < 4; mf++) {
        const int r = m0 + rm + mf * 16 + (lane >> 2);
#pragma unroll
        for (int nf = 0; nf < 8; nf++) {
            const int cidx = n0 + rn + nf * 8 + (lane & 3) * 2;
            size_t g0 = (size_t)r * HID + cidx;
            float2 v0 = __half22float2(*reinterpret_cast<__half2*>(&acc[mf][nf][0]));
            float2 x0 = *reinterpret_cast<const float2*>(x_cur + g0);
            float2 o0;
            o0.x = fmaf(alpha, v0.x, x0.x);
            o0.y = fmaf(alpha, v0.y, x0.y);
            *reinterpret_cast<float2*>(out + g0) = o0;
            size_t g1 = g0 + (size_t)8 * HID;
            float2 v1 = __half22float2(*reinterpret_cast<__half2*>(&acc[mf][nf][1]));
            float2 x1 = *reinterpret_cast<const float2*>(x_cur + g1);
            float2 o1;
            o1.x = fmaf(alpha, v1.x, x1.x);
            o1.y = fmaf(alpha, v1.y, x1.y);
            *reinterpret_cast<float2*>(out + g1) = o1;
        }
    }
}

// -------------------- launcher ---------------------------------------------
extern "C" void kernel_launch(void* const* d_in, const int* in_sizes, int n_in,
                              void* d_out, int out_size) {
    const float* x_cur  = (const float*)d_in[0];
    const float* x_prev = (const float*)d_in[1];
    const float* alpha  = (const float*)d_in[2];
    const float* vals   = (const float*)d_in[3];
    const int*   idx    = (const int*)d_in[4];
    const int nnz   = in_sizes[3];
    const int mrows = in_sizes[0] / HID;     // 8192

    cudaFuncSetAttribute(gemm_kernel,
                         cudaFuncAttributeMaxDynamicSharedMemorySize, SMEM_BYTES);

    const int n16x = mrows * HID / 16;
    zero_and_convx_kernel<<<2048, 256>>>(x_prev, n16x);
    scatter_kernel<<<(nnz + 255) / 256, 256>>>(idx, vals, nnz);
    conv_w_kernel<<<(HID * HID / 16 + 255) / 256, 256>>>();

    dim3 grid(HID / BN, mrows / BM);         // 16 x 64 = 1024 CTAs
    gemm_kernel<<<grid, NTHREADS, SMEM_BYTES>>>(x_cur, alpha, (float*)d_out);
}